// round 14
// baseline (speedup 1.0000x reference)
#include <cuda_runtime.h>
#include <cuda_fp16.h>
#include <math.h>
#include <stdint.h>

// Shapes (fixed): B=2, S=2048, E=1024, H=16, D=64
// Fragment-image planes (blocks = hi-plane | lo-plane):
//  g_xA : x as A op (bf16)   [mb(32)][kt(32)] blocks of 16KB (hi8K|lo8K)
//  g_OA : attn out as A op (fp16; only hi used) same layout
//  g_WkB/g_WvB: weights as B op (bf16) [nb(8)][kt(32)] blocks of 16KB
//  g_WoB: Wo as B op (fp16; only hi used) same layout
//  g_KA : K as A op (bf16)   [hb(32)][mb(16)][dc(2)] blocks of 16KB
//  g_VSB: V as S-GEMM B op (bf16) [hb(32)][kb(32)][dc(2)] blocks of 8KB (hi4K|lo4K)
//  g_VPB: V as PV-GEMM B op (fp16 hi only) [hb(32)][kc(64)] blocks of 4KB
static __device__ float g_xA[8 * 1024 * 1024];
static __device__ float g_OA[8 * 1024 * 1024];
static __device__ float g_WkB[2 * 1024 * 1024];
static __device__ float g_WvB[2 * 1024 * 1024];
static __device__ float g_WoB[2 * 1024 * 1024];
static __device__ float g_KA[8 * 1024 * 1024];
static __device__ float g_VSB[8 * 1024 * 1024];
static __device__ float g_VPB[2 * 1024 * 1024];

__device__ __forceinline__ float fast_exp2(float x) {
    float y;
    asm("ex2.approx.ftz.f32 %0, %1;" : "=f"(y) : "f"(x));
    return y;
}
// bf16 helpers (v0 -> low half)
__device__ __forceinline__ uint32_t bf16x2_pack(float v0, float v1) {
    uint32_t r;
    asm("cvt.rn.bf16x2.f32 %0, %1, %2;" : "=r"(r) : "f"(v1), "f"(v0));
    return r;
}
__device__ __forceinline__ void bf16_split(float v0, float v1, uint32_t& hw,
                                           uint32_t& lw) {
    hw = bf16x2_pack(v0, v1);
    float h0 = __uint_as_float(hw << 16);
    float h1 = __uint_as_float(hw & 0xFFFF0000u);
    lw = bf16x2_pack(v0 - h0, v1 - h1);
}
// fp16 helpers (v0 -> low half)
__device__ __forceinline__ uint32_t f16x2_pack(float v0, float v1) {
    __half2 h = __floats2half2_rn(v0, v1);
    return *reinterpret_cast<uint32_t*>(&h);
}
__device__ __forceinline__ void f16_split(float v0, float v1, uint32_t& hw,
                                          uint32_t& lw) {
    __half2 h = __floats2half2_rn(v0, v1);
    hw = *reinterpret_cast<uint32_t*>(&h);
    float r0 = v0 - __low2float(h);
    float r1 = v1 - __high2float(h);
    __half2 l = __floats2half2_rn(r0, r1);
    lw = *reinterpret_cast<uint32_t*>(&l);
}

__device__ __forceinline__ void mma_bf16(float c[4], const uint32_t a[4],
                                         const uint32_t b[2]) {
    asm volatile(
        "mma.sync.aligned.m16n8k16.row.col.f32.bf16.bf16.f32 "
        "{%0,%1,%2,%3}, {%4,%5,%6,%7}, {%8,%9}, {%0,%1,%2,%3};"
        : "+f"(c[0]), "+f"(c[1]), "+f"(c[2]), "+f"(c[3])
        : "r"(a[0]), "r"(a[1]), "r"(a[2]), "r"(a[3]), "r"(b[0]), "r"(b[1]));
}
__device__ __forceinline__ void mma_f16(float c[4], const uint32_t a[4],
                                        const uint32_t b[2]) {
    asm volatile(
        "mma.sync.aligned.m16n8k16.row.col.f32.f16.f16.f32 "
        "{%0,%1,%2,%3}, {%4,%5,%6,%7}, {%8,%9}, {%0,%1,%2,%3};"
        : "+f"(c[0]), "+f"(c[1]), "+f"(c[2]), "+f"(c[3])
        : "r"(a[0]), "r"(a[1]), "r"(a[2]), "r"(a[3]), "r"(b[0]), "r"(b[1]));
}
__device__ __forceinline__ uint32_t smem_u32(const void* p) {
    uint32_t a;
    asm("{ .reg .u64 t; cvta.to.shared.u64 t, %1; cvt.u32.u64 %0, t; }"
        : "=r"(a) : "l"(p));
    return a;
}

#define SW128(o) ((o) ^ (((o) >> 3) & 0x70))
#define CP16(d, s) \
    asm volatile("cp.async.cg.shared.global [%0], [%1], 16;" ::"r"(d), "l"(s) : "memory")
#define CP_COMMIT() asm volatile("cp.async.commit_group;" ::: "memory")
#define CP_WAIT(n) asm volatile("cp.async.wait_group %0;" ::"n"(n) : "memory")

// ---- 16-bit image word offsets (p = k>>1, pair index within 32-k tile) ----
// A-plane 8KB: 128 rows x 32 k
__device__ __forceinline__ uint32_t A16_off(int row, int p) {
    int kc = p >> 3, pi = p & 7;
    uint32_t base = (uint32_t)(kc * 8 + (row >> 4)) << 9;
    uint32_t lane = (uint32_t)(((row & 7) << 2) | (pi & 3));
    uint32_t w = (uint32_t)(((pi >> 2) << 1) | ((row >> 3) & 1));
    return SW128(base + (lane << 4) + (w << 2));
}
// B-plane 8KB: 128 n x 32 k
__device__ __forceinline__ uint32_t B16_off(int n, int p) {
    int kc = p >> 3, pi = p & 7;
    uint32_t base = (uint32_t)(kc * 16 + (n >> 3)) << 8;
    uint32_t lane = (uint32_t)(((n & 7) << 2) | (pi & 3));
    uint32_t w = (uint32_t)(pi >> 2);
    return SW128(base + (lane << 3) + (w << 2));
}
// B-plane 4KB: 64 n x 32 k
__device__ __forceinline__ uint32_t B16_off64(int n, int p) {
    int kc = p >> 3, pi = p & 7;
    uint32_t base = (uint32_t)(kc * 8 + (n >> 3)) << 8;
    uint32_t lane = (uint32_t)(((n & 7) << 2) | (pi & 3));
    uint32_t w = (uint32_t)(pi >> 2);
    return SW128(base + (lane << 3) + (w << 2));
}

// ---------------------------------------------------------------------------
// Split kernel: fp32 -> hi/lo fragment images.
// z=0: x -> bf16 A-images; z=1,2: Wk/Wv -> bf16 B-images; z=3: Wo -> fp16.
// ---------------------------------------------------------------------------
__global__ __launch_bounds__(128) void split_kernel(const float* __restrict__ x,
                                                    const float* __restrict__ Wk,
                                                    const float* __restrict__ Wv,
                                                    const float* __restrict__ Wo) {
    const int z = blockIdx.z;
    const int mb = blockIdx.y;
    const int kt = blockIdx.x;
    const float* src;
    float* dst;
    int isA;
    if (z == 0) {
        src = x; dst = g_xA; isA = 1;
    } else {
        if (mb >= 8) return;
        src = (z == 1) ? Wk : (z == 2) ? Wv : Wo;
        dst = (z == 1) ? g_WkB : (z == 2) ? g_WvB : g_WoB;
        isA = 0;
    }
    char* blk = (char*)dst + (size_t)(mb * 32 + kt) * 16384;
    const int tid = threadIdx.x;
#pragma unroll
    for (int e = 0; e < 16; e++) {
        int idx = e * 128 + tid;
        int row = idx >> 4;
        int p = idx & 15;
        const float* r = src + (size_t)(mb * 128 + row) * 1024 + kt * 32 + p * 2;
        uint32_t hw, lw;
        if (z == 3) f16_split(r[0], r[1], hw, lw);
        else bf16_split(r[0], r[1], hw, lw);
        uint32_t off = isA ? A16_off(row, p) : B16_off(row, p);
        *reinterpret_cast<uint32_t*>(blk + off) = hw;
        *reinterpret_cast<uint32_t*>(blk + 8192 + off) = lw;
    }
}

// ---------------------------------------------------------------------------
// Image GEMM: CTA 128x128, K=1024. 256 threads = 8 warps = 4(M) x 2(N),
// warp tile 32x64. 3-stage cp.async, one barrier per K-tile, fragment
// double-buffering, pass-major issue.
// WMODE 1/2 (proj K/V): bf16 3-pass (hh + hl + lh), 32KB stages.
// WMODE 0  (oproj):     fp16 1-pass (Ah·Bh); HI PLANES ONLY, 16KB stages.
// ---------------------------------------------------------------------------
#define GM_SMEM_BYTES_PROJ (3 * 32768)
#define GM_SMEM_BYTES_OPROJ (3 * 16384)

__device__ __forceinline__ void wr_K_img(int m, int col, float v0, float v1) {
    int s = m & 2047;
    int hb = ((m >> 11) << 4) + (col >> 6);
    int d = col & 63;
    char* blk = (char*)g_KA +
                (size_t)((hb * 16 + (s >> 7)) * 2 + (d >> 5)) * 16384;
    uint32_t off = A16_off(s & 127, (d & 31) >> 1);
    uint32_t hw, lw;
    bf16_split(v0, v1, hw, lw);
    *reinterpret_cast<uint32_t*>(blk + off) = hw;
    *reinterpret_cast<uint32_t*>(blk + 8192 + off) = lw;
}
__device__ __forceinline__ void wr_V_img(int m, int col, float v0, float v1) {
    int s = m & 2047;
    int hb = ((m >> 11) << 4) + (col >> 6);
    int d = col & 63;
    {   // VSB: bf16, n = key (64), k = d (32)
        char* blk = (char*)g_VSB +
                    (size_t)((hb * 32 + (s >> 6)) * 2 + (d >> 5)) * 8192;
        uint32_t off = B16_off64(s & 63, (d & 31) >> 1);
        uint32_t hw, lw;
        bf16_split(v0, v1, hw, lw);
        *reinterpret_cast<uint32_t*>(blk + off) = hw;
        *reinterpret_cast<uint32_t*>(blk + 4096 + off) = lw;
    }
    {   // VPB: fp16 HI ONLY, n = d (64), k = key (32). Adjacent keys live in
        // adjacent g-lanes (lane ^ 4); even-g lanes pack (key s, key s+1).
        float u0 = __shfl_xor_sync(0xffffffffu, v0, 4);
        float u1 = __shfl_xor_sync(0xffffffffu, v1, 4);
        int lane = (int)(threadIdx.x & 31);
        if (!(lane & 4)) {
            char* blk = (char*)g_VPB + (size_t)(hb * 64 + (s >> 5)) * 4096;
            uint32_t p = (uint32_t)((s & 31) >> 1);
            *reinterpret_cast<uint32_t*>(blk + B16_off64(d, p)) =
                f16x2_pack(v0, u0);
            *reinterpret_cast<uint32_t*>(blk + B16_off64(d + 1, p)) =
                f16x2_pack(v1, u1);
        }
    }
}

template <int WMODE>
__device__ void gemm_img_body(const float* __restrict__ Aimg,
                              const float* __restrict__ Bimg,
                              float* __restrict__ Cout) {
    extern __shared__ __align__(1024) char smc[];
    const uint32_t sbase = smem_u32(smc);
    const int tid = threadIdx.x;
    const int lane = tid & 31;
    const int wid = tid >> 5;
    const int warpM = wid & 3;
    const int warpN = wid >> 2;
    const int mb = blockIdx.y;
    const int nb = blockIdx.x;

    constexpr uint32_t STG_SZ = (WMODE == 0) ? 16384u : 32768u;
    constexpr uint32_t B_OFF = (WMODE == 0) ? 8192u : 16384u;

    float c[2][8][4];
#pragma unroll
    for (int i = 0; i < 2; i++)
#pragma unroll
        for (int j = 0; j < 8; j++)
#pragma unroll
            for (int q = 0; q < 4; q++) c[i][j][q] = 0.0f;

    uint32_t ah[2][2][4], al[2][2][4], bh[2][8][2], bl[2][8][2];

    const char* Abase = (const char*)(Aimg) + (size_t)mb * 32 * 16384;
    const char* Bbase = (const char*)(Bimg) + (size_t)nb * 32 * 16384;

    auto issue = [&](int kt) {
        int st = kt % 3;
        if (WMODE == 0) {
            // hi planes only: A-hi 8KB + B-hi 8KB per stage
            if (tid < 128) {
                uint32_t d = sbase + (uint32_t)st * STG_SZ + (uint32_t)tid * 64;
                const char* s = Abase + (size_t)kt * 16384 + tid * 64;
#pragma unroll
                for (int j = 0; j < 4; j++) CP16(d + j * 16, s + j * 16);
            } else {
                uint32_t d = sbase + (uint32_t)st * STG_SZ + B_OFF +
                             (uint32_t)(tid - 128) * 64;
                const char* s = Bbase + (size_t)kt * 16384 + (tid - 128) * 64;
#pragma unroll
                for (int j = 0; j < 4; j++) CP16(d + j * 16, s + j * 16);
            }
        } else {
            if (tid < 128) {
                uint32_t d = sbase + (uint32_t)st * STG_SZ + (uint32_t)tid * 128;
                const char* s = Abase + (size_t)kt * 16384 + tid * 128;
#pragma unroll
                for (int j = 0; j < 8; j++) CP16(d + j * 16, s + j * 16);
            } else {
                uint32_t d = sbase + (uint32_t)st * STG_SZ + B_OFF +
                             (uint32_t)(tid - 128) * 128;
                const char* s = Bbase + (size_t)kt * 16384 + (tid - 128) * 128;
#pragma unroll
                for (int j = 0; j < 8; j++) CP16(d + j * 16, s + j * 16);
            }
        }
        CP_COMMIT();
    };

    auto ldfrag = [&](const char* smb, int kc, int buf) {
#pragma unroll
        for (int tm = 0; tm < 2; tm++) {
            uint32_t off = SW128((uint32_t)(kc * 8 + warpM * 2 + tm) * 512 + lane * 16);
            uint4 h = *reinterpret_cast<const uint4*>(smb + off);
            ah[buf][tm][0] = h.x; ah[buf][tm][1] = h.y;
            ah[buf][tm][2] = h.z; ah[buf][tm][3] = h.w;
            if (WMODE != 0) {
                uint4 l = *reinterpret_cast<const uint4*>(smb + 8192 + off);
                al[buf][tm][0] = l.x; al[buf][tm][1] = l.y;
                al[buf][tm][2] = l.z; al[buf][tm][3] = l.w;
            }
        }
#pragma unroll
        for (int tn = 0; tn < 8; tn++) {
            uint32_t off = SW128((uint32_t)(kc * 16 + warpN * 8 + tn) * 256 + lane * 8);
            uint2 h = *reinterpret_cast<const uint2*>(smb + B_OFF + off);
            bh[buf][tn][0] = h.x; bh[buf][tn][1] = h.y;
            if (WMODE != 0) {
                uint2 l = *reinterpret_cast<const uint2*>(smb + B_OFF + 8192 + off);
                bl[buf][tn][0] = l.x; bl[buf][tn][1] = l.y;
            }
        }
    };

    issue(0);
    issue(1);
    for (int kt = 0; kt < 32; kt++) {
        if (kt < 31) CP_WAIT(1); else CP_WAIT(0);
        __syncthreads();
        if (kt + 2 < 32) issue(kt + 2);
        const char* smb = smc + (uint32_t)(kt % 3) * STG_SZ;

        ldfrag(smb, 0, 0);
#pragma unroll
        for (int kc = 0; kc < 2; kc++) {
            const int cur = kc & 1;
            if (kc < 1) ldfrag(smb, kc + 1, cur ^ 1);
            if (WMODE == 0) {
                // fp16 1-pass: Ah·Bh
#pragma unroll
                for (int tm = 0; tm < 2; tm++)
#pragma unroll
                    for (int tn = 0; tn < 8; tn++)
                        mma_f16(c[tm][tn], ah[cur][tm], bh[cur][tn]);
            } else {
                // bf16 3-pass: Ah·Bh + Ah·Bl + Al·Bh
#pragma unroll
                for (int tm = 0; tm < 2; tm++)
#pragma unroll
                    for (int tn = 0; tn < 8; tn++)
                        mma_bf16(c[tm][tn], ah[cur][tm], bh[cur][tn]);
#pragma unroll
                for (int tm = 0; tm < 2; tm++)
#pragma unroll
                    for (int tn = 0; tn < 8; tn++)
                        mma_bf16(c[tm][tn], ah[cur][tm], bl[cur][tn]);
#pragma unroll
                for (int tm = 0; tm < 2; tm++)
#pragma unroll
                    for (int tn = 0; tn < 8; tn++)
                        mma_bf16(c[tm][tn], al[cur][tm], bh[cur][tn]);
            }
        }
    }

    const int g = lane >> 2;
    const int t4 = lane & 3;
    const int bm = mb * 128;
    const int bn = nb * 128;
#pragma unroll
    for (int tm = 0; tm < 2; tm++) {
#pragma unroll
        for (int tn = 0; tn < 8; tn++) {
            int row0 = bm + warpM * 32 + tm * 16 + g;
            int col = bn + warpN * 64 + tn * 8 + t4 * 2;
#pragma unroll
            for (int hrow = 0; hrow < 2; hrow++) {
                int m = row0 + hrow * 8;
                float v0 = c[tm][tn][2 * hrow];
                float v1 = c[tm][tn][2 * hrow + 1];
                if (WMODE == 1) {
                    wr_K_img(m, col, v0, v1);
                } else if (WMODE == 2) {
                    wr_V_img(m, col, v0, v1);
                } else {
                    *reinterpret_cast<float2*>(Cout + (size_t)m * 1024 + col) =
                        make_float2(v0, v1);
                }
            }
        }
    }
}

__global__ __launch_bounds__(256, 1) void proj_img_kernel() {
    if (blockIdx.z == 0)
        gemm_img_body<1>(g_xA, g_WkB, nullptr);
    else
        gemm_img_body<2>(g_xA, g_WvB, nullptr);
}
__global__ __launch_bounds__(256, 1) void oproj_img_kernel(float* __restrict__ out) {
    gemm_img_body<0>(g_OA, g_WoB, out);
}

// ---------------------------------------------------------------------------
// Tensor-core attention, 128-KEY TILES (16 iterations):
//   S = K·V^T in 3x-bf16 (two 64-key halves); one softmax per 128 keys;
//   O += P_fp16 · V_fp16hi (1 pass, 8 k16 steps).
// l sums the SAME fp16-quantized p values the MMA consumes.
// Per (b,h), q-block of 128 rows (CTA). 256 thr = 8 warps; warp w owns rows
// w*16..w*16+15. Single-buffered fragments (R9: double-buffering = neutral).
// SMEM: K bf16 32KB | P fp16 32KB | 2 stages x (VSB 32KB + VPB 16KB) = 160KB
// ---------------------------------------------------------------------------
#define ATT_K 0
#define ATT_P 32768
#define ATT_STG 65536
#define ATT_STAGE_SZ 49152
#define ATT_SMEM_BYTES (65536 + 2 * ATT_STAGE_SZ)

__global__ __launch_bounds__(256, 1) void attn_mma_kernel() {
    extern __shared__ __align__(1024) char smc[];
    const uint32_t sbase = smem_u32(smc);
    const int tid = threadIdx.x;
    const int lane = tid & 31;
    const int w = tid >> 5;
    const int g = lane >> 2;
    const int t4 = lane & 3;
    const int hb = blockIdx.y;
    const int mb = blockIdx.x;
    const float SC = -32.0f * 1.4426950408889634f;

    const char* KAg = (const char*)g_KA + (size_t)(hb * 16 + mb) * 32768;
    const char* VSBg = (const char*)g_VSB + (size_t)hb * 32 * 16384;
    const char* VPBg = (const char*)g_VPB + (size_t)hb * 64 * 4096;

    // Stage: VSB 32KB (4 x 8KB blocks: [kb0,dc0][kb0,dc1][kb1,dc0][kb1,dc1])
    //        then VPB 16KB (4 x 4KB blocks kc=4i..4i+3).
    auto issue_stage = [&](int i) {
        uint32_t stg = sbase + (uint32_t)(ATT_STG + (i & 1) * ATT_STAGE_SZ);
        {
            uint32_t d = stg + (uint32_t)tid * 128;
            const char* s = VSBg + (size_t)i * 32768 + tid * 128;
#pragma unroll
            for (int j = 0; j < 8; j++) CP16(d + j * 16, s + j * 16);
        }
        {
            uint32_t d = stg + 32768 + (uint32_t)tid * 64;
            const char* s = VPBg + (size_t)i * 16384 + tid * 64;
#pragma unroll
            for (int j = 0; j < 4; j++) CP16(d + j * 16, s + j * 16);
        }
        CP_COMMIT();
    };

    // Prologue: K (32KB, joins group 0) + stage0, then stage1
    {
        uint32_t d = sbase + (uint32_t)tid * 128;
        const char* s = KAg + tid * 128;
#pragma unroll
        for (int j = 0; j < 8; j++) CP16(d + j * 16, s + j * 16);
    }
    issue_stage(0);
    issue_stage(1);

    float o[8][4];
#pragma unroll
    for (int tn = 0; tn < 8; tn++)
#pragma unroll
        for (int q = 0; q < 4; q++) o[tn][q] = 0.0f;
    float m0 = -INFINITY, m1 = -INFINITY, l0 = 0.0f, l1 = 0.0f;

    for (int i = 0; i < 16; i++) {
        if (i < 15) CP_WAIT(1); else CP_WAIT(0);
        __syncthreads();
        const uint32_t stg = (uint32_t)(ATT_STG + (i & 1) * ATT_STAGE_SZ);

        // ---- S = K·V^T (128 rows x 128 keys), 3x-bf16, two 64-key halves ----
        float s[16][4];
#pragma unroll
        for (int tn = 0; tn < 16; tn++)
#pragma unroll
            for (int q = 0; q < 4; q++) s[tn][q] = 0.0f;

#pragma unroll
        for (int h = 0; h < 2; h++) {
            float(*sh)[4] = s + h * 8;
#pragma unroll
            for (int kc = 0; kc < 4; kc++) {
                int dc = kc >> 1;
                int kci = kc & 1;
                uint32_t ah[4], al[4], bh[8][2], bl[8][2];
                uint32_t aoff = (uint32_t)(ATT_K + dc * 16384) +
                                SW128((uint32_t)(kci * 8 + w) * 512 + lane * 16);
                uint4 h4 = *reinterpret_cast<const uint4*>(smc + aoff);
                uint4 l4 = *reinterpret_cast<const uint4*>(smc + aoff + 8192);
                ah[0] = h4.x; ah[1] = h4.y; ah[2] = h4.z; ah[3] = h4.w;
                al[0] = l4.x; al[1] = l4.y; al[2] = l4.z; al[3] = l4.w;
#pragma unroll
                for (int tn = 0; tn < 8; tn++) {
                    uint32_t boff = stg + (uint32_t)((h * 2 + dc) * 8192) +
                                    SW128((uint32_t)(kci * 8 + tn) * 256 + lane * 8);
                    uint2 bh2 = *reinterpret_cast<const uint2*>(smc + boff);
                    uint2 bl2 = *reinterpret_cast<const uint2*>(smc + boff + 4096);
                    bh[tn][0] = bh2.x; bh[tn][1] = bh2.y;
                    bl[tn][0] = bl2.x; bl[tn][1] = bl2.y;
                }
#pragma unroll
                for (int tn = 0; tn < 8; tn++) mma_bf16(sh[tn], ah, bh[tn]);
#pragma unroll
                for (int tn = 0; tn < 8; tn++) mma_bf16(sh[tn], ah, bl[tn]);
#pragma unroll
                for (int tn = 0; tn < 8; tn++) mma_bf16(sh[tn], al, bh[tn]);
            }
        }

        // ---- softmax over this 128-key tile (rows: w*16+g, w*16+g+8) ----
#pragma unroll
        for (int tn = 0; tn < 16; tn++)
#pragma unroll
            for (int q = 0; q < 4; q++) s[tn][q] *= SC;

        float mx0 = s[0][0], mx1 = s[0][2];
#pragma unroll
        for (int tn = 0; tn < 16; tn++) {
            mx0 = fmaxf(mx0, fmaxf(s[tn][0], s[tn][1]));
            mx1 = fmaxf(mx1, fmaxf(s[tn][2], s[tn][3]));
        }
        mx0 = fmaxf(mx0, __shfl_xor_sync(0xffffffffu, mx0, 1));
        mx0 = fmaxf(mx0, __shfl_xor_sync(0xffffffffu, mx0, 2));
        mx1 = fmaxf(mx1, __shfl_xor_sync(0xffffffffu, mx1, 1));
        mx1 = fmaxf(mx1, __shfl_xor_sync(0xffffffffu, mx1, 2));

        float mn0 = fmaxf(m0, mx0), mn1 = fmaxf(m1, mx1);
        float al0 = fast_exp2(m0 - mn0), al1 = fast_exp2(m1 - mn1);
        m0 = mn0; m1 = mn1;

        // Quantize p to fp16, pack two adjacent keys per thread into one
        // fp16x2 P-image word, sum quantized values into l.
        float rs0 = 0.0f, rs1 = 0.0f;
        const int r0 = w * 16 + g;
#pragma unroll
        for (int tn = 0; tn < 16; tn++) {
            int pairIdx = tn * 4 + t4;  // 0..63 (keys 2*pairIdx, 2*pairIdx+1)
#pragma unroll
            for (int hrow = 0; hrow < 2; hrow++) {
                float mnv = hrow ? mn1 : mn0;
                float p0 = fast_exp2(s[tn][2 * hrow] - mnv);
                float p1 = fast_exp2(s[tn][2 * hrow + 1] - mnv);
                __half2 ph = __floats2half2_rn(p0, p1);
                uint32_t pw = *reinterpret_cast<uint32_t*>(&ph);
                float pq0 = __low2float(ph);
                float pq1 = __high2float(ph);
                if (hrow) rs1 += pq0 + pq1; else rs0 += pq0 + pq1;
                int row = r0 + hrow * 8;
                *reinterpret_cast<uint32_t*>(
                    smc + ATT_P + (pairIdx >> 4) * 8192 +
                    A16_off(row, pairIdx & 15)) = pw;
            }
        }
        rs0 += __shfl_xor_sync(0xffffffffu, rs0, 1);
        rs0 += __shfl_xor_sync(0xffffffffu, rs0, 2);
        rs1 += __shfl_xor_sync(0xffffffffu, rs1, 1);
        rs1 += __shfl_xor_sync(0xffffffffu, rs1, 2);
        l0 = l0 * al0 + rs0;
        l1 = l1 * al1 + rs1;
#pragma unroll
        for (int tn = 0; tn < 8; tn++) {
            o[tn][0] *= al0; o[tn][1] *= al0;
            o[tn][2] *= al1; o[tn][3] *= al1;
        }
        __syncwarp();

        // ---- O += P_fp16 · V_fp16hi (128 keys = 8 k16 steps) ----
#pragma unroll
        for (int kk = 0; kk < 8; kk++) {
            uint32_t pa[4], vh[8][2];
            uint32_t poff = (uint32_t)(ATT_P + (kk >> 1) * 8192) +
                            SW128((uint32_t)((kk & 1) * 8 + w) * 512 + lane * 16);
            uint4 p4 = *reinterpret_cast<const uint4*>(smc + poff);
            pa[0] = p4.x; pa[1] = p4.y; pa[2] = p4.z; pa[3] = p4.w;
#pragma unroll
            for (int tn = 0; tn < 8; tn++) {
                uint32_t voff = stg + (uint32_t)(32768 + (kk >> 1) * 4096) +
                                SW128((uint32_t)((kk & 1) * 8 + tn) * 256 + lane * 8);
                uint2 vh2 = *reinterpret_cast<const uint2*>(smc + voff);
                vh[tn][0] = vh2.x; vh[tn][1] = vh2.y;
            }
#pragma unroll
            for (int tn = 0; tn < 8; tn++) mma_f16(o[tn], pa, vh[tn]);
        }
        __syncthreads();
        if (i < 14) issue_stage(i + 2);
    }

    // ---- epilogue: normalize and write g_OA fp16 A-images (HI plane only) ----
    const int b = hb >> 4;
    const int h = hb & 15;
    const float inv0 = 1.0f / l0, inv1 = 1.0f / l1;
    const int rbase = b * 2048 + mb * 128 + w * 16 + g;
#pragma unroll
    for (int tn = 0; tn < 8; tn++) {
        int d0 = h * 64 + tn * 8 + t4 * 2;
#pragma unroll
        for (int hrow = 0; hrow < 2; hrow++) {
            int row = rbase + hrow * 8;
            float inv = hrow ? inv1 : inv0;
            float v0 = o[tn][2 * hrow] * inv;
            float v1 = o[tn][2 * hrow + 1] * inv;
            char* blk = (char*)g_OA + (size_t)((row >> 7) * 32 + (d0 >> 5)) * 16384;
            uint32_t off = A16_off(row & 127, (d0 & 31) >> 1);
            *reinterpret_cast<uint32_t*>(blk + off) = f16x2_pack(v0, v1);
        }
    }
}

extern "C" void kernel_launch(void* const* d_in, const int* in_sizes, int n_in,
                              void* d_out, int out_size) {
    const float* x = (const float*)d_in[0];
    // d_in[1] = Wq (dead code in the reference dataflow)
    const float* Wk = (const float*)d_in[2];
    const float* Wv = (const float*)d_in[3];
    const float* Wo = (const float*)d_in[4];
    float* out = (float*)d_out;

    cudaFuncSetAttribute(proj_img_kernel, cudaFuncAttributeMaxDynamicSharedMemorySize,
                         GM_SMEM_BYTES_PROJ);
    cudaFuncSetAttribute(oproj_img_kernel, cudaFuncAttributeMaxDynamicSharedMemorySize,
                         GM_SMEM_BYTES_OPROJ);
    cudaFuncSetAttribute(attn_mma_kernel, cudaFuncAttributeMaxDynamicSharedMemorySize,
                         ATT_SMEM_BYTES);

    // 1) Pre-split inputs into fragment images (x/Wk/Wv bf16, Wo fp16)
    split_kernel<<<dim3(32, 32, 4), 128>>>(x, Wk, Wv, Wo);

    // 2) K/V projections (3x-bf16); epilogues write K/V attention images
    proj_img_kernel<<<dim3(8, 32, 2), 256, GM_SMEM_BYTES_PROJ>>>();

    // 3) Tensor-core attention (S: 3x-bf16, PV: 1x-fp16, 128-key tiles)
    attn_mma_kernel<<<dim3(16, 32), 256, ATT_SMEM_BYTES>>>();

    // 4) Output projection (1x-fp16, hi planes only)
    oproj_img_kernel<<<dim3(8, 32), 256, GM_SMEM_BYTES_OPROJ>>>(out);
}

// round 15
// speedup vs baseline: 1.0872x; 1.0872x over previous
#include <cuda_runtime.h>
#include <cuda_fp16.h>
#include <math.h>
#include <stdint.h>

// Shapes (fixed): B=2, S=2048, E=1024, H=16, D=64
// Fragment-image planes (blocks = hi-plane | lo-plane):
//  g_xA : x as A op (bf16)   [mb(32)][kt(32)] blocks of 16KB (hi8K|lo8K)
//  g_OA : attn out as A op (fp16; only hi used) same layout
//  g_WkB/g_WvB: weights as B op (bf16) [nb(8)][kt(32)] blocks of 16KB
//  g_WoB: Wo as B op (fp16; only hi used) same layout
//  g_KA : K as A op (bf16)   [hb(32)][mb(16)][dc(2)] blocks of 16KB
//  g_VSB: V as S-GEMM B op (bf16) [hb(32)][kb(32)][dc(2)] blocks of 8KB (hi4K|lo4K)
//  g_VPB: V as PV-GEMM B op (fp16 hi only) [hb(32)][kc(64)] blocks of 4KB
static __device__ float g_xA[8 * 1024 * 1024];
static __device__ float g_OA[8 * 1024 * 1024];
static __device__ float g_WkB[2 * 1024 * 1024];
static __device__ float g_WvB[2 * 1024 * 1024];
static __device__ float g_WoB[2 * 1024 * 1024];
static __device__ float g_KA[8 * 1024 * 1024];
static __device__ float g_VSB[8 * 1024 * 1024];
static __device__ float g_VPB[2 * 1024 * 1024];

__device__ __forceinline__ float fast_exp2(float x) {
    float y;
    asm("ex2.approx.ftz.f32 %0, %1;" : "=f"(y) : "f"(x));
    return y;
}
// bf16 helpers (v0 -> low half)
__device__ __forceinline__ uint32_t bf16x2_pack(float v0, float v1) {
    uint32_t r;
    asm("cvt.rn.bf16x2.f32 %0, %1, %2;" : "=r"(r) : "f"(v1), "f"(v0));
    return r;
}
__device__ __forceinline__ void bf16_split(float v0, float v1, uint32_t& hw,
                                           uint32_t& lw) {
    hw = bf16x2_pack(v0, v1);
    float h0 = __uint_as_float(hw << 16);
    float h1 = __uint_as_float(hw & 0xFFFF0000u);
    lw = bf16x2_pack(v0 - h0, v1 - h1);
}
// fp16 helpers (v0 -> low half)
__device__ __forceinline__ uint32_t f16x2_pack(float v0, float v1) {
    __half2 h = __floats2half2_rn(v0, v1);
    return *reinterpret_cast<uint32_t*>(&h);
}
__device__ __forceinline__ void f16_split(float v0, float v1, uint32_t& hw,
                                          uint32_t& lw) {
    __half2 h = __floats2half2_rn(v0, v1);
    hw = *reinterpret_cast<uint32_t*>(&h);
    float r0 = v0 - __low2float(h);
    float r1 = v1 - __high2float(h);
    __half2 l = __floats2half2_rn(r0, r1);
    lw = *reinterpret_cast<uint32_t*>(&l);
}

__device__ __forceinline__ void mma_bf16(float c[4], const uint32_t a[4],
                                         const uint32_t b[2]) {
    asm volatile(
        "mma.sync.aligned.m16n8k16.row.col.f32.bf16.bf16.f32 "
        "{%0,%1,%2,%3}, {%4,%5,%6,%7}, {%8,%9}, {%0,%1,%2,%3};"
        : "+f"(c[0]), "+f"(c[1]), "+f"(c[2]), "+f"(c[3])
        : "r"(a[0]), "r"(a[1]), "r"(a[2]), "r"(a[3]), "r"(b[0]), "r"(b[1]));
}
__device__ __forceinline__ void mma_f16(float c[4], const uint32_t a[4],
                                        const uint32_t b[2]) {
    asm volatile(
        "mma.sync.aligned.m16n8k16.row.col.f32.f16.f16.f32 "
        "{%0,%1,%2,%3}, {%4,%5,%6,%7}, {%8,%9}, {%0,%1,%2,%3};"
        : "+f"(c[0]), "+f"(c[1]), "+f"(c[2]), "+f"(c[3])
        : "r"(a[0]), "r"(a[1]), "r"(a[2]), "r"(a[3]), "r"(b[0]), "r"(b[1]));
}
__device__ __forceinline__ uint32_t smem_u32(const void* p) {
    uint32_t a;
    asm("{ .reg .u64 t; cvta.to.shared.u64 t, %1; cvt.u32.u64 %0, t; }"
        : "=r"(a) : "l"(p));
    return a;
}

#define SW128(o) ((o) ^ (((o) >> 3) & 0x70))
#define CP16(d, s) \
    asm volatile("cp.async.cg.shared.global [%0], [%1], 16;" ::"r"(d), "l"(s) : "memory")
#define CP_COMMIT() asm volatile("cp.async.commit_group;" ::: "memory")
#define CP_WAIT(n) asm volatile("cp.async.wait_group %0;" ::"n"(n) : "memory")

// ---- 16-bit image word offsets (p = k>>1, pair index within 32-k tile) ----
// A-plane 8KB: 128 rows x 32 k
__device__ __forceinline__ uint32_t A16_off(int row, int p) {
    int kc = p >> 3, pi = p & 7;
    uint32_t base = (uint32_t)(kc * 8 + (row >> 4)) << 9;
    uint32_t lane = (uint32_t)(((row & 7) << 2) | (pi & 3));
    uint32_t w = (uint32_t)(((pi >> 2) << 1) | ((row >> 3) & 1));
    return SW128(base + (lane << 4) + (w << 2));
}
// B-plane 8KB: 128 n x 32 k
__device__ __forceinline__ uint32_t B16_off(int n, int p) {
    int kc = p >> 3, pi = p & 7;
    uint32_t base = (uint32_t)(kc * 16 + (n >> 3)) << 8;
    uint32_t lane = (uint32_t)(((n & 7) << 2) | (pi & 3));
    uint32_t w = (uint32_t)(pi >> 2);
    return SW128(base + (lane << 3) + (w << 2));
}
// B-plane 4KB: 64 n x 32 k
__device__ __forceinline__ uint32_t B16_off64(int n, int p) {
    int kc = p >> 3, pi = p & 7;
    uint32_t base = (uint32_t)(kc * 8 + (n >> 3)) << 8;
    uint32_t lane = (uint32_t)(((n & 7) << 2) | (pi & 3));
    uint32_t w = (uint32_t)(pi >> 2);
    return SW128(base + (lane << 3) + (w << 2));
}

// ---------------------------------------------------------------------------
// Split kernel: fp32 -> hi/lo fragment images.
// z=0: x -> bf16 A-images; z=1,2: Wk/Wv -> bf16 B-images; z=3: Wo -> fp16.
// ---------------------------------------------------------------------------
__global__ __launch_bounds__(128) void split_kernel(const float* __restrict__ x,
                                                    const float* __restrict__ Wk,
                                                    const float* __restrict__ Wv,
                                                    const float* __restrict__ Wo) {
    const int z = blockIdx.z;
    const int mb = blockIdx.y;
    const int kt = blockIdx.x;
    const float* src;
    float* dst;
    int isA;
    if (z == 0) {
        src = x; dst = g_xA; isA = 1;
    } else {
        if (mb >= 8) return;
        src = (z == 1) ? Wk : (z == 2) ? Wv : Wo;
        dst = (z == 1) ? g_WkB : (z == 2) ? g_WvB : g_WoB;
        isA = 0;
    }
    char* blk = (char*)dst + (size_t)(mb * 32 + kt) * 16384;
    const int tid = threadIdx.x;
#pragma unroll
    for (int e = 0; e < 16; e++) {
        int idx = e * 128 + tid;
        int row = idx >> 4;
        int p = idx & 15;
        const float* r = src + (size_t)(mb * 128 + row) * 1024 + kt * 32 + p * 2;
        uint32_t hw, lw;
        if (z == 3) f16_split(r[0], r[1], hw, lw);
        else bf16_split(r[0], r[1], hw, lw);
        uint32_t off = isA ? A16_off(row, p) : B16_off(row, p);
        *reinterpret_cast<uint32_t*>(blk + off) = hw;
        *reinterpret_cast<uint32_t*>(blk + 8192 + off) = lw;
    }
}

// ---------------------------------------------------------------------------
// Image GEMM: CTA 128x128, K=1024. 256 threads = 8 warps = 4(M) x 2(N),
// warp tile 32x64. 3-stage cp.async, one barrier per K-tile, SINGLE-buffered
// fragments (R9: double-buffering neutral; frees regs for 2 CTAs/SM).
// WMODE 1/2 (proj K/V): bf16 3-pass (hh + hl + lh), 32KB stages.
// WMODE 0  (oproj):     fp16 1-pass (Ah·Bh); HI PLANES ONLY, 16KB stages.
// ---------------------------------------------------------------------------
#define GM_SMEM_BYTES_PROJ (3 * 32768)
#define GM_SMEM_BYTES_OPROJ (3 * 16384)

__device__ __forceinline__ void wr_K_img(int m, int col, float v0, float v1) {
    int s = m & 2047;
    int hb = ((m >> 11) << 4) + (col >> 6);
    int d = col & 63;
    char* blk = (char*)g_KA +
                (size_t)((hb * 16 + (s >> 7)) * 2 + (d >> 5)) * 16384;
    uint32_t off = A16_off(s & 127, (d & 31) >> 1);
    uint32_t hw, lw;
    bf16_split(v0, v1, hw, lw);
    *reinterpret_cast<uint32_t*>(blk + off) = hw;
    *reinterpret_cast<uint32_t*>(blk + 8192 + off) = lw;
}
__device__ __forceinline__ void wr_V_img(int m, int col, float v0, float v1) {
    int s = m & 2047;
    int hb = ((m >> 11) << 4) + (col >> 6);
    int d = col & 63;
    {   // VSB: bf16, n = key (64), k = d (32)
        char* blk = (char*)g_VSB +
                    (size_t)((hb * 32 + (s >> 6)) * 2 + (d >> 5)) * 8192;
        uint32_t off = B16_off64(s & 63, (d & 31) >> 1);
        uint32_t hw, lw;
        bf16_split(v0, v1, hw, lw);
        *reinterpret_cast<uint32_t*>(blk + off) = hw;
        *reinterpret_cast<uint32_t*>(blk + 4096 + off) = lw;
    }
    {   // VPB: fp16 HI ONLY, n = d (64), k = key (32). Adjacent keys live in
        // adjacent g-lanes (lane ^ 4); even-g lanes pack (key s, key s+1).
        float u0 = __shfl_xor_sync(0xffffffffu, v0, 4);
        float u1 = __shfl_xor_sync(0xffffffffu, v1, 4);
        int lane = (int)(threadIdx.x & 31);
        if (!(lane & 4)) {
            char* blk = (char*)g_VPB + (size_t)(hb * 64 + (s >> 5)) * 4096;
            uint32_t p = (uint32_t)((s & 31) >> 1);
            *reinterpret_cast<uint32_t*>(blk + B16_off64(d, p)) =
                f16x2_pack(v0, u0);
            *reinterpret_cast<uint32_t*>(blk + B16_off64(d + 1, p)) =
                f16x2_pack(v1, u1);
        }
    }
}

template <int WMODE>
__device__ void gemm_img_body(const float* __restrict__ Aimg,
                              const float* __restrict__ Bimg,
                              float* __restrict__ Cout) {
    extern __shared__ __align__(1024) char smc[];
    const uint32_t sbase = smem_u32(smc);
    const int tid = threadIdx.x;
    const int lane = tid & 31;
    const int wid = tid >> 5;
    const int warpM = wid & 3;
    const int warpN = wid >> 2;
    const int mb = blockIdx.y;
    const int nb = blockIdx.x;

    constexpr uint32_t STG_SZ = (WMODE == 0) ? 16384u : 32768u;
    constexpr uint32_t B_OFF = (WMODE == 0) ? 8192u : 16384u;

    float c[2][8][4];
#pragma unroll
    for (int i = 0; i < 2; i++)
#pragma unroll
        for (int j = 0; j < 8; j++)
#pragma unroll
            for (int q = 0; q < 4; q++) c[i][j][q] = 0.0f;

    uint32_t ah[2][4], al[2][4], bh[8][2], bl[8][2];

    const char* Abase = (const char*)(Aimg) + (size_t)mb * 32 * 16384;
    const char* Bbase = (const char*)(Bimg) + (size_t)nb * 32 * 16384;

    auto issue = [&](int kt) {
        int st = kt % 3;
        if (WMODE == 0) {
            // hi planes only: A-hi 8KB + B-hi 8KB per stage
            if (tid < 128) {
                uint32_t d = sbase + (uint32_t)st * STG_SZ + (uint32_t)tid * 64;
                const char* s = Abase + (size_t)kt * 16384 + tid * 64;
#pragma unroll
                for (int j = 0; j < 4; j++) CP16(d + j * 16, s + j * 16);
            } else {
                uint32_t d = sbase + (uint32_t)st * STG_SZ + B_OFF +
                             (uint32_t)(tid - 128) * 64;
                const char* s = Bbase + (size_t)kt * 16384 + (tid - 128) * 64;
#pragma unroll
                for (int j = 0; j < 4; j++) CP16(d + j * 16, s + j * 16);
            }
        } else {
            if (tid < 128) {
                uint32_t d = sbase + (uint32_t)st * STG_SZ + (uint32_t)tid * 128;
                const char* s = Abase + (size_t)kt * 16384 + tid * 128;
#pragma unroll
                for (int j = 0; j < 8; j++) CP16(d + j * 16, s + j * 16);
            } else {
                uint32_t d = sbase + (uint32_t)st * STG_SZ + B_OFF +
                             (uint32_t)(tid - 128) * 128;
                const char* s = Bbase + (size_t)kt * 16384 + (tid - 128) * 128;
#pragma unroll
                for (int j = 0; j < 8; j++) CP16(d + j * 16, s + j * 16);
            }
        }
        CP_COMMIT();
    };

    auto ldfrag = [&](const char* smb, int kc) {
#pragma unroll
        for (int tm = 0; tm < 2; tm++) {
            uint32_t off = SW128((uint32_t)(kc * 8 + warpM * 2 + tm) * 512 + lane * 16);
            uint4 h = *reinterpret_cast<const uint4*>(smb + off);
            ah[tm][0] = h.x; ah[tm][1] = h.y; ah[tm][2] = h.z; ah[tm][3] = h.w;
            if (WMODE != 0) {
                uint4 l = *reinterpret_cast<const uint4*>(smb + 8192 + off);
                al[tm][0] = l.x; al[tm][1] = l.y; al[tm][2] = l.z; al[tm][3] = l.w;
            }
        }
#pragma unroll
        for (int tn = 0; tn < 8; tn++) {
            uint32_t off = SW128((uint32_t)(kc * 16 + warpN * 8 + tn) * 256 + lane * 8);
            uint2 h = *reinterpret_cast<const uint2*>(smb + B_OFF + off);
            bh[tn][0] = h.x; bh[tn][1] = h.y;
            if (WMODE != 0) {
                uint2 l = *reinterpret_cast<const uint2*>(smb + B_OFF + 8192 + off);
                bl[tn][0] = l.x; bl[tn][1] = l.y;
            }
        }
    };

    issue(0);
    issue(1);
    for (int kt = 0; kt < 32; kt++) {
        if (kt < 31) CP_WAIT(1); else CP_WAIT(0);
        __syncthreads();
        if (kt + 2 < 32) issue(kt + 2);
        const char* smb = smc + (uint32_t)(kt % 3) * STG_SZ;

#pragma unroll
        for (int kc = 0; kc < 2; kc++) {
            ldfrag(smb, kc);
            if (WMODE == 0) {
                // fp16 1-pass: Ah·Bh
#pragma unroll
                for (int tm = 0; tm < 2; tm++)
#pragma unroll
                    for (int tn = 0; tn < 8; tn++)
                        mma_f16(c[tm][tn], ah[tm], bh[tn]);
            } else {
                // bf16 3-pass: Ah·Bh + Ah·Bl + Al·Bh
#pragma unroll
                for (int tm = 0; tm < 2; tm++)
#pragma unroll
                    for (int tn = 0; tn < 8; tn++)
                        mma_bf16(c[tm][tn], ah[tm], bh[tn]);
#pragma unroll
                for (int tm = 0; tm < 2; tm++)
#pragma unroll
                    for (int tn = 0; tn < 8; tn++)
                        mma_bf16(c[tm][tn], ah[tm], bl[tn]);
#pragma unroll
                for (int tm = 0; tm < 2; tm++)
#pragma unroll
                    for (int tn = 0; tn < 8; tn++)
                        mma_bf16(c[tm][tn], al[tm], bh[tn]);
            }
        }
    }

    const int g = lane >> 2;
    const int t4 = lane & 3;
    const int bm = mb * 128;
    const int bn = nb * 128;
#pragma unroll
    for (int tm = 0; tm < 2; tm++) {
#pragma unroll
        for (int tn = 0; tn < 8; tn++) {
            int row0 = bm + warpM * 32 + tm * 16 + g;
            int col = bn + warpN * 64 + tn * 8 + t4 * 2;
#pragma unroll
            for (int hrow = 0; hrow < 2; hrow++) {
                int m = row0 + hrow * 8;
                float v0 = c[tm][tn][2 * hrow];
                float v1 = c[tm][tn][2 * hrow + 1];
                if (WMODE == 1) {
                    wr_K_img(m, col, v0, v1);
                } else if (WMODE == 2) {
                    wr_V_img(m, col, v0, v1);
                } else {
                    *reinterpret_cast<float2*>(Cout + (size_t)m * 1024 + col) =
                        make_float2(v0, v1);
                }
            }
        }
    }
}

__global__ __launch_bounds__(256, 2) void proj_img_kernel() {
    if (blockIdx.z == 0)
        gemm_img_body<1>(g_xA, g_WkB, nullptr);
    else
        gemm_img_body<2>(g_xA, g_WvB, nullptr);
}
__global__ __launch_bounds__(256, 2) void oproj_img_kernel(float* __restrict__ out) {
    gemm_img_body<0>(g_OA, g_WoB, out);
}

// ---------------------------------------------------------------------------
// Tensor-core attention (R13 structure, 64-key tiles):
//   S = K·V^T in 3x-bf16 (k16); softmax; O += P_fp16 · V_fp16hi (1 pass).
// Single-buffered fragments; __launch_bounds__(256,2) for 2 CTAs/SM so the
// co-resident CTA's MMAs cover this CTA's softmax windows and the wave tail.
// SMEM: K bf16 32KB | P fp16 16KB | 2 stages x (VSB 16KB + VPB 8KB) = 96KB
// ---------------------------------------------------------------------------
#define ATT_K 0
#define ATT_P 32768
#define ATT_STG 49152
#define ATT_STAGE_SZ 24576
#define ATT_SMEM_BYTES (49152 + 2 * ATT_STAGE_SZ)

__global__ __launch_bounds__(256, 2) void attn_mma_kernel() {
    extern __shared__ __align__(1024) char smc[];
    const uint32_t sbase = smem_u32(smc);
    const int tid = threadIdx.x;
    const int lane = tid & 31;
    const int w = tid >> 5;
    const int g = lane >> 2;
    const int t4 = lane & 3;
    const int hb = blockIdx.y;
    const int mb = blockIdx.x;
    const float SC = -32.0f * 1.4426950408889634f;

    const char* KAg = (const char*)g_KA + (size_t)(hb * 16 + mb) * 32768;
    const char* VSBg = (const char*)g_VSB + (size_t)hb * 32 * 16384;
    const char* VPBg = (const char*)g_VPB + (size_t)hb * 64 * 4096;

    auto issue_stage = [&](int i) {
        uint32_t stg = (uint32_t)(ATT_STG + (i & 1) * ATT_STAGE_SZ);
        if (tid < 128) {
            uint32_t d = sbase + stg + (uint32_t)tid * 128;
            const char* s = VSBg + (size_t)i * 16384 + tid * 128;
#pragma unroll
            for (int j = 0; j < 8; j++) CP16(d + j * 16, s + j * 16);
        } else {
            uint32_t d = sbase + stg + 16384 + (uint32_t)(tid - 128) * 64;
            const char* s = VPBg + (size_t)(2 * i) * 4096 + (tid - 128) * 64;
#pragma unroll
            for (int j = 0; j < 4; j++) CP16(d + j * 16, s + j * 16);
        }
        CP_COMMIT();
    };

    // Prologue: K (32KB, joins group 0) + stage0, then stage1
    {
        uint32_t d = sbase + (uint32_t)tid * 128;
        const char* s = KAg + tid * 128;
#pragma unroll
        for (int j = 0; j < 8; j++) CP16(d + j * 16, s + j * 16);
    }
    issue_stage(0);
    issue_stage(1);

    float o[8][4];
#pragma unroll
    for (int tn = 0; tn < 8; tn++)
#pragma unroll
        for (int q = 0; q < 4; q++) o[tn][q] = 0.0f;
    float m0 = -INFINITY, m1 = -INFINITY, l0 = 0.0f, l1 = 0.0f;

    for (int i = 0; i < 32; i++) {
        if (i < 31) CP_WAIT(1); else CP_WAIT(0);
        __syncthreads();
        const uint32_t stg = (uint32_t)(ATT_STG + (i & 1) * ATT_STAGE_SZ);

        // ---- S = K·V^T (128 x 64), 3x-bf16, single-buffered frags ----
        float s[8][4];
#pragma unroll
        for (int tn = 0; tn < 8; tn++)
#pragma unroll
            for (int q = 0; q < 4; q++) s[tn][q] = 0.0f;

        uint32_t ah[4], al[4], bh[8][2], bl[8][2];
#pragma unroll
        for (int kc = 0; kc < 4; kc++) {
            int dc = kc >> 1;   // which 32-d chunk (16KB block)
            int kci = kc & 1;   // k16 chunk within block
            uint32_t aoff = (uint32_t)(ATT_K + dc * 16384) +
                            SW128((uint32_t)(kci * 8 + w) * 512 + lane * 16);
            uint4 h4 = *reinterpret_cast<const uint4*>(smc + aoff);
            uint4 l4 = *reinterpret_cast<const uint4*>(smc + aoff + 8192);
            ah[0] = h4.x; ah[1] = h4.y; ah[2] = h4.z; ah[3] = h4.w;
            al[0] = l4.x; al[1] = l4.y; al[2] = l4.z; al[3] = l4.w;
#pragma unroll
            for (int tn = 0; tn < 8; tn++) {
                uint32_t boff = stg + (uint32_t)(dc * 8192) +
                                SW128((uint32_t)(kci * 8 + tn) * 256 + lane * 8);
                uint2 bh2 = *reinterpret_cast<const uint2*>(smc + boff);
                uint2 bl2 = *reinterpret_cast<const uint2*>(smc + boff + 4096);
                bh[tn][0] = bh2.x; bh[tn][1] = bh2.y;
                bl[tn][0] = bl2.x; bl[tn][1] = bl2.y;
            }
#pragma unroll
            for (int tn = 0; tn < 8; tn++) mma_bf16(s[tn], ah, bh[tn]);
#pragma unroll
            for (int tn = 0; tn < 8; tn++) mma_bf16(s[tn], ah, bl[tn]);
#pragma unroll
            for (int tn = 0; tn < 8; tn++) mma_bf16(s[tn], al, bh[tn]);
        }

        // ---- softmax over this 64-key tile (rows: w*16+g, w*16+g+8) ----
#pragma unroll
        for (int tn = 0; tn < 8; tn++)
#pragma unroll
            for (int q = 0; q < 4; q++) s[tn][q] *= SC;

        float mx0 = s[0][0], mx1 = s[0][2];
#pragma unroll
        for (int tn = 0; tn < 8; tn++) {
            mx0 = fmaxf(mx0, fmaxf(s[tn][0], s[tn][1]));
            mx1 = fmaxf(mx1, fmaxf(s[tn][2], s[tn][3]));
        }
        mx0 = fmaxf(mx0, __shfl_xor_sync(0xffffffffu, mx0, 1));
        mx0 = fmaxf(mx0, __shfl_xor_sync(0xffffffffu, mx0, 2));
        mx1 = fmaxf(mx1, __shfl_xor_sync(0xffffffffu, mx1, 1));
        mx1 = fmaxf(mx1, __shfl_xor_sync(0xffffffffu, mx1, 2));

        float mn0 = fmaxf(m0, mx0), mn1 = fmaxf(m1, mx1);
        float al0 = fast_exp2(m0 - mn0), al1 = fast_exp2(m1 - mn1);
        m0 = mn0; m1 = mn1;

        // Quantize p to fp16 (the exact values the PV MMA consumes), pack two
        // adjacent keys per thread into one fp16x2 P-image word, sum quantized
        // values into l.
        float rs0 = 0.0f, rs1 = 0.0f;
        const int r0 = w * 16 + g;
#pragma unroll
        for (int tn = 0; tn < 8; tn++) {
            int pairIdx = tn * 4 + t4;  // 0..31 (keys 2*pairIdx, 2*pairIdx+1)
#pragma unroll
            for (int hrow = 0; hrow < 2; hrow++) {
                float mnv = hrow ? mn1 : mn0;
                float p0 = fast_exp2(s[tn][2 * hrow] - mnv);
                float p1 = fast_exp2(s[tn][2 * hrow + 1] - mnv);
                __half2 ph = __floats2half2_rn(p0, p1);
                uint32_t pw = *reinterpret_cast<uint32_t*>(&ph);
                float pq0 = __low2float(ph);
                float pq1 = __high2float(ph);
                if (hrow) rs1 += pq0 + pq1; else rs0 += pq0 + pq1;
                int row = r0 + hrow * 8;
                *reinterpret_cast<uint32_t*>(
                    smc + ATT_P + (pairIdx >> 4) * 8192 +
                    A16_off(row, pairIdx & 15)) = pw;
            }
        }
        rs0 += __shfl_xor_sync(0xffffffffu, rs0, 1);
        rs0 += __shfl_xor_sync(0xffffffffu, rs0, 2);
        rs1 += __shfl_xor_sync(0xffffffffu, rs1, 1);
        rs1 += __shfl_xor_sync(0xffffffffu, rs1, 2);
        l0 = l0 * al0 + rs0;
        l1 = l1 * al1 + rs1;
#pragma unroll
        for (int tn = 0; tn < 8; tn++) {
            o[tn][0] *= al0; o[tn][1] *= al0;
            o[tn][2] *= al1; o[tn][3] *= al1;
        }
        __syncwarp();

        // ---- O += P_fp16 · V_fp16hi (single pass), single-buffered frags ----
#pragma unroll
        for (int kk = 0; kk < 4; kk++) {
            int kc = kk >> 1;   // 32-key chunk
            int kci = kk & 1;   // k16 within chunk
            uint32_t pa[4], vh[8][2];
            uint32_t poff = (uint32_t)(ATT_P + kc * 8192) +
                            SW128((uint32_t)(kci * 8 + w) * 512 + lane * 16);
            uint4 p4 = *reinterpret_cast<const uint4*>(smc + poff);
            pa[0] = p4.x; pa[1] = p4.y; pa[2] = p4.z; pa[3] = p4.w;
#pragma unroll
            for (int tn = 0; tn < 8; tn++) {
                uint32_t voff = stg + (uint32_t)(16384 + kc * 4096) +
                                SW128((uint32_t)(kci * 8 + tn) * 256 + lane * 8);
                uint2 vh2 = *reinterpret_cast<const uint2*>(smc + voff);
                vh[tn][0] = vh2.x; vh[tn][1] = vh2.y;
            }
#pragma unroll
            for (int tn = 0; tn < 8; tn++) mma_f16(o[tn], pa, vh[tn]);
        }
        __syncthreads();
        if (i < 30) issue_stage(i + 2);
    }

    // ---- epilogue: normalize and write g_OA fp16 A-images (HI plane only) ----
    const int b = hb >> 4;
    const int h = hb & 15;
    const float inv0 = 1.0f / l0, inv1 = 1.0f / l1;
    const int rbase = b * 2048 + mb * 128 + w * 16 + g;
#pragma unroll
    for (int tn = 0; tn < 8; tn++) {
        int d0 = h * 64 + tn * 8 + t4 * 2;
#pragma unroll
        for (int hrow = 0; hrow < 2; hrow++) {
            int row = rbase + hrow * 8;
            float inv = hrow ? inv1 : inv0;
            float v0 = o[tn][2 * hrow] * inv;
            float v1 = o[tn][2 * hrow + 1] * inv;
            char* blk = (char*)g_OA + (size_t)((row >> 7) * 32 + (d0 >> 5)) * 16384;
            uint32_t off = A16_off(row & 127, (d0 & 31) >> 1);
            *reinterpret_cast<uint32_t*>(blk + off) = f16x2_pack(v0, v1);
        }
    }
}

extern "C" void kernel_launch(void* const* d_in, const int* in_sizes, int n_in,
                              void* d_out, int out_size) {
    const float* x = (const float*)d_in[0];
    // d_in[1] = Wq (dead code in the reference dataflow)
    const float* Wk = (const float*)d_in[2];
    const float* Wv = (const float*)d_in[3];
    const float* Wo = (const float*)d_in[4];
    float* out = (float*)d_out;

    cudaFuncSetAttribute(proj_img_kernel, cudaFuncAttributeMaxDynamicSharedMemorySize,
                         GM_SMEM_BYTES_PROJ);
    cudaFuncSetAttribute(oproj_img_kernel, cudaFuncAttributeMaxDynamicSharedMemorySize,
                         GM_SMEM_BYTES_OPROJ);
    cudaFuncSetAttribute(attn_mma_kernel, cudaFuncAttributeMaxDynamicSharedMemorySize,
                         ATT_SMEM_BYTES);

    // 1) Pre-split inputs into fragment images (x/Wk/Wv bf16, Wo fp16)
    split_kernel<<<dim3(32, 32, 4), 128>>>(x, Wk, Wv, Wo);

    // 2) K/V projections (3x-bf16); epilogues write K/V attention images
    proj_img_kernel<<<dim3(8, 32, 2), 256, GM_SMEM_BYTES_PROJ>>>();

    // 3) Tensor-core attention (S: 3x-bf16, PV: 1x-fp16), writes g_OA hi images
    attn_mma_kernel<<<dim3(16, 32), 256, ATT_SMEM_BYTES>>>();

    // 4) Output projection (1x-fp16, hi planes only)
    oproj_img_kernel<<<dim3(8, 32), 256, GM_SMEM_BYTES_OPROJ>>>(out);
}

// round 16
// speedup vs baseline: 1.2031x; 1.1067x over previous
#include <cuda_runtime.h>
#include <cuda_fp16.h>
#include <math.h>
#include <stdint.h>

// Shapes (fixed): B=2, S=2048, E=1024, H=16, D=64
// Fragment-image planes (blocks = hi-plane | lo-plane):
//  g_xA : x as A op (bf16)   [mb(32)][kt(32)] blocks of 16KB (hi8K|lo8K)
//  g_OA : attn out as A op (fp16; only hi used) same layout
//  g_WkB/g_WvB: weights as B op (bf16) [nb(8)][kt(32)] blocks of 16KB
//  g_WoB: Wo as B op (fp16; only hi used) same layout
//  g_KA : K as A op (bf16)   [hb(32)][mb(16)][dc(2)] blocks of 16KB
//  g_VSB: V as S-GEMM B op (bf16) [hb(32)][kb(32)][dc(2)] blocks of 8KB (hi4K|lo4K)
//  g_VPB: V as PV-GEMM B op (fp16 hi only) [hb(32)][kc(64)] blocks of 4KB
static __device__ float g_xA[8 * 1024 * 1024];
static __device__ float g_OA[8 * 1024 * 1024];
static __device__ float g_WkB[2 * 1024 * 1024];
static __device__ float g_WvB[2 * 1024 * 1024];
static __device__ float g_WoB[2 * 1024 * 1024];
static __device__ float g_KA[8 * 1024 * 1024];
static __device__ float g_VSB[8 * 1024 * 1024];
static __device__ float g_VPB[2 * 1024 * 1024];

// Megakernel work-queue state (zeroed by init_kernel each launch)
static __device__ int g_next;
static __device__ int g_projdone[32];  // index: z*16 + nb*2 + b ; target 16
static __device__ int g_attndone[32];  // index: b*16 + mbq      ; target 16

__device__ __forceinline__ float fast_exp2(float x) {
    float y;
    asm("ex2.approx.ftz.f32 %0, %1;" : "=f"(y) : "f"(x));
    return y;
}
// bf16 helpers (v0 -> low half)
__device__ __forceinline__ uint32_t bf16x2_pack(float v0, float v1) {
    uint32_t r;
    asm("cvt.rn.bf16x2.f32 %0, %1, %2;" : "=r"(r) : "f"(v1), "f"(v0));
    return r;
}
__device__ __forceinline__ void bf16_split(float v0, float v1, uint32_t& hw,
                                           uint32_t& lw) {
    hw = bf16x2_pack(v0, v1);
    float h0 = __uint_as_float(hw << 16);
    float h1 = __uint_as_float(hw & 0xFFFF0000u);
    lw = bf16x2_pack(v0 - h0, v1 - h1);
}
// fp16 helpers (v0 -> low half)
__device__ __forceinline__ uint32_t f16x2_pack(float v0, float v1) {
    __half2 h = __floats2half2_rn(v0, v1);
    return *reinterpret_cast<uint32_t*>(&h);
}
__device__ __forceinline__ void f16_split(float v0, float v1, uint32_t& hw,
                                          uint32_t& lw) {
    __half2 h = __floats2half2_rn(v0, v1);
    hw = *reinterpret_cast<uint32_t*>(&h);
    float r0 = v0 - __low2float(h);
    float r1 = v1 - __high2float(h);
    __half2 l = __floats2half2_rn(r0, r1);
    lw = *reinterpret_cast<uint32_t*>(&l);
}

__device__ __forceinline__ void mma_bf16(float c[4], const uint32_t a[4],
                                         const uint32_t b[2]) {
    asm volatile(
        "mma.sync.aligned.m16n8k16.row.col.f32.bf16.bf16.f32 "
        "{%0,%1,%2,%3}, {%4,%5,%6,%7}, {%8,%9}, {%0,%1,%2,%3};"
        : "+f"(c[0]), "+f"(c[1]), "+f"(c[2]), "+f"(c[3])
        : "r"(a[0]), "r"(a[1]), "r"(a[2]), "r"(a[3]), "r"(b[0]), "r"(b[1]));
}
__device__ __forceinline__ void mma_f16(float c[4], const uint32_t a[4],
                                        const uint32_t b[2]) {
    asm volatile(
        "mma.sync.aligned.m16n8k16.row.col.f32.f16.f16.f32 "
        "{%0,%1,%2,%3}, {%4,%5,%6,%7}, {%8,%9}, {%0,%1,%2,%3};"
        : "+f"(c[0]), "+f"(c[1]), "+f"(c[2]), "+f"(c[3])
        : "r"(a[0]), "r"(a[1]), "r"(a[2]), "r"(a[3]), "r"(b[0]), "r"(b[1]));
}
__device__ __forceinline__ uint32_t smem_u32(const void* p) {
    uint32_t a;
    asm("{ .reg .u64 t; cvta.to.shared.u64 t, %1; cvt.u32.u64 %0, t; }"
        : "=r"(a) : "l"(p));
    return a;
}

#define SW128(o) ((o) ^ (((o) >> 3) & 0x70))
#define CP16(d, s) \
    asm volatile("cp.async.cg.shared.global [%0], [%1], 16;" ::"r"(d), "l"(s) : "memory")
#define CP_COMMIT() asm volatile("cp.async.commit_group;" ::: "memory")
#define CP_WAIT(n) asm volatile("cp.async.wait_group %0;" ::"n"(n) : "memory")

// ---- 16-bit image word offsets (p = k>>1, pair index within 32-k tile) ----
__device__ __forceinline__ uint32_t A16_off(int row, int p) {
    int kc = p >> 3, pi = p & 7;
    uint32_t base = (uint32_t)(kc * 8 + (row >> 4)) << 9;
    uint32_t lane = (uint32_t)(((row & 7) << 2) | (pi & 3));
    uint32_t w = (uint32_t)(((pi >> 2) << 1) | ((row >> 3) & 1));
    return SW128(base + (lane << 4) + (w << 2));
}
__device__ __forceinline__ uint32_t B16_off(int n, int p) {
    int kc = p >> 3, pi = p & 7;
    uint32_t base = (uint32_t)(kc * 16 + (n >> 3)) << 8;
    uint32_t lane = (uint32_t)(((n & 7) << 2) | (pi & 3));
    uint32_t w = (uint32_t)(pi >> 2);
    return SW128(base + (lane << 3) + (w << 2));
}
__device__ __forceinline__ uint32_t B16_off64(int n, int p) {
    int kc = p >> 3, pi = p & 7;
    uint32_t base = (uint32_t)(kc * 8 + (n >> 3)) << 8;
    uint32_t lane = (uint32_t)(((n & 7) << 2) | (pi & 3));
    uint32_t w = (uint32_t)(pi >> 2);
    return SW128(base + (lane << 3) + (w << 2));
}

// ---------------------------------------------------------------------------
// Split kernel (separate launch): fp32 -> hi/lo fragment images.
// ---------------------------------------------------------------------------
__global__ __launch_bounds__(128) void split_kernel(const float* __restrict__ x,
                                                    const float* __restrict__ Wk,
                                                    const float* __restrict__ Wv,
                                                    const float* __restrict__ Wo) {
    const int z = blockIdx.z;
    const int mb = blockIdx.y;
    const int kt = blockIdx.x;
    const float* src;
    float* dst;
    int isA;
    if (z == 0) {
        src = x; dst = g_xA; isA = 1;
    } else {
        if (mb >= 8) return;
        src = (z == 1) ? Wk : (z == 2) ? Wv : Wo;
        dst = (z == 1) ? g_WkB : (z == 2) ? g_WvB : g_WoB;
        isA = 0;
    }
    char* blk = (char*)dst + (size_t)(mb * 32 + kt) * 16384;
    const int tid = threadIdx.x;
#pragma unroll
    for (int e = 0; e < 16; e++) {
        int idx = e * 128 + tid;
        int row = idx >> 4;
        int p = idx & 15;
        const float* r = src + (size_t)(mb * 128 + row) * 1024 + kt * 32 + p * 2;
        uint32_t hw, lw;
        if (z == 3) f16_split(r[0], r[1], hw, lw);
        else bf16_split(r[0], r[1], hw, lw);
        uint32_t off = isA ? A16_off(row, p) : B16_off(row, p);
        *reinterpret_cast<uint32_t*>(blk + off) = hw;
        if (z != 3) *reinterpret_cast<uint32_t*>(blk + 8192 + off) = lw;
    }
}

__global__ void init_kernel() {
    int i = threadIdx.x;
    if (i == 0) g_next = 0;
    if (i < 32) {
        g_projdone[i] = 0;
        g_attndone[i] = 0;
    }
}

// ---------------------------------------------------------------------------
// Image GEMM item: CTA tile 128x128, K=1024. 256 thr = 8 warps = 4(M)x2(N),
// warp tile 32x64. 3-stage cp.async, single-buffered fragments, pass-major.
// WMODE 1/2 (proj K/V): bf16 3-pass, 32KB stages. WMODE 0 (oproj): fp16
// 1-pass, hi planes only, 16KB stages.
// ---------------------------------------------------------------------------
#define MEGA_SMEM_BYTES (3 * 32768)

__device__ __forceinline__ void wr_K_img(int m, int col, float v0, float v1) {
    int s = m & 2047;
    int hb = ((m >> 11) << 4) + (col >> 6);
    int d = col & 63;
    char* blk = (char*)g_KA +
                (size_t)((hb * 16 + (s >> 7)) * 2 + (d >> 5)) * 16384;
    uint32_t off = A16_off(s & 127, (d & 31) >> 1);
    uint32_t hw, lw;
    bf16_split(v0, v1, hw, lw);
    *reinterpret_cast<uint32_t*>(blk + off) = hw;
    *reinterpret_cast<uint32_t*>(blk + 8192 + off) = lw;
}
__device__ __forceinline__ void wr_V_img(int m, int col, float v0, float v1) {
    int s = m & 2047;
    int hb = ((m >> 11) << 4) + (col >> 6);
    int d = col & 63;
    {   // VSB: bf16, n = key (64), k = d (32)
        char* blk = (char*)g_VSB +
                    (size_t)((hb * 32 + (s >> 6)) * 2 + (d >> 5)) * 8192;
        uint32_t off = B16_off64(s & 63, (d & 31) >> 1);
        uint32_t hw, lw;
        bf16_split(v0, v1, hw, lw);
        *reinterpret_cast<uint32_t*>(blk + off) = hw;
        *reinterpret_cast<uint32_t*>(blk + 4096 + off) = lw;
    }
    {   // VPB: fp16 HI ONLY, n = d (64), k = key (32)
        float u0 = __shfl_xor_sync(0xffffffffu, v0, 4);
        float u1 = __shfl_xor_sync(0xffffffffu, v1, 4);
        int lane = (int)(threadIdx.x & 31);
        if (!(lane & 4)) {
            char* blk = (char*)g_VPB + (size_t)(hb * 64 + (s >> 5)) * 4096;
            uint32_t p = (uint32_t)((s & 31) >> 1);
            *reinterpret_cast<uint32_t*>(blk + B16_off64(d, p)) =
                f16x2_pack(v0, u0);
            *reinterpret_cast<uint32_t*>(blk + B16_off64(d + 1, p)) =
                f16x2_pack(v1, u1);
        }
    }
}

template <int WMODE>
__device__ void gemm_img_body(const float* __restrict__ Aimg,
                              const float* __restrict__ Bimg,
                              float* __restrict__ Cout, int mb, int nb) {
    extern __shared__ __align__(1024) char smc[];
    const uint32_t sbase = smem_u32(smc);
    const int tid = threadIdx.x;
    const int lane = tid & 31;
    const int wid = tid >> 5;
    const int warpM = wid & 3;
    const int warpN = wid >> 2;

    constexpr uint32_t STG_SZ = (WMODE == 0) ? 16384u : 32768u;
    constexpr uint32_t B_OFF = (WMODE == 0) ? 8192u : 16384u;

    float c[2][8][4];
#pragma unroll
    for (int i = 0; i < 2; i++)
#pragma unroll
        for (int j = 0; j < 8; j++)
#pragma unroll
            for (int q = 0; q < 4; q++) c[i][j][q] = 0.0f;

    uint32_t ah[2][4], al[2][4], bh[8][2], bl[8][2];

    const char* Abase = (const char*)(Aimg) + (size_t)mb * 32 * 16384;
    const char* Bbase = (const char*)(Bimg) + (size_t)nb * 32 * 16384;

    auto issue = [&](int kt) {
        int st = kt % 3;
        if (WMODE == 0) {
            if (tid < 128) {
                uint32_t d = sbase + (uint32_t)st * STG_SZ + (uint32_t)tid * 64;
                const char* s = Abase + (size_t)kt * 16384 + tid * 64;
#pragma unroll
                for (int j = 0; j < 4; j++) CP16(d + j * 16, s + j * 16);
            } else {
                uint32_t d = sbase + (uint32_t)st * STG_SZ + B_OFF +
                             (uint32_t)(tid - 128) * 64;
                const char* s = Bbase + (size_t)kt * 16384 + (tid - 128) * 64;
#pragma unroll
                for (int j = 0; j < 4; j++) CP16(d + j * 16, s + j * 16);
            }
        } else {
            if (tid < 128) {
                uint32_t d = sbase + (uint32_t)st * STG_SZ + (uint32_t)tid * 128;
                const char* s = Abase + (size_t)kt * 16384 + tid * 128;
#pragma unroll
                for (int j = 0; j < 8; j++) CP16(d + j * 16, s + j * 16);
            } else {
                uint32_t d = sbase + (uint32_t)st * STG_SZ + B_OFF +
                             (uint32_t)(tid - 128) * 128;
                const char* s = Bbase + (size_t)kt * 16384 + (tid - 128) * 128;
#pragma unroll
                for (int j = 0; j < 8; j++) CP16(d + j * 16, s + j * 16);
            }
        }
        CP_COMMIT();
    };

    auto ldfrag = [&](const char* smb, int kc) {
#pragma unroll
        for (int tm = 0; tm < 2; tm++) {
            uint32_t off = SW128((uint32_t)(kc * 8 + warpM * 2 + tm) * 512 + lane * 16);
            uint4 h = *reinterpret_cast<const uint4*>(smb + off);
            ah[tm][0] = h.x; ah[tm][1] = h.y; ah[tm][2] = h.z; ah[tm][3] = h.w;
            if (WMODE != 0) {
                uint4 l = *reinterpret_cast<const uint4*>(smb + 8192 + off);
                al[tm][0] = l.x; al[tm][1] = l.y; al[tm][2] = l.z; al[tm][3] = l.w;
            }
        }
#pragma unroll
        for (int tn = 0; tn < 8; tn++) {
            uint32_t off = SW128((uint32_t)(kc * 16 + warpN * 8 + tn) * 256 + lane * 8);
            uint2 h = *reinterpret_cast<const uint2*>(smb + B_OFF + off);
            bh[tn][0] = h.x; bh[tn][1] = h.y;
            if (WMODE != 0) {
                uint2 l = *reinterpret_cast<const uint2*>(smb + B_OFF + 8192 + off);
                bl[tn][0] = l.x; bl[tn][1] = l.y;
            }
        }
    };

    issue(0);
    issue(1);
    for (int kt = 0; kt < 32; kt++) {
        if (kt < 31) CP_WAIT(1); else CP_WAIT(0);
        __syncthreads();
        if (kt + 2 < 32) issue(kt + 2);
        const char* smb = smc + (uint32_t)(kt % 3) * STG_SZ;

#pragma unroll
        for (int kc = 0; kc < 2; kc++) {
            ldfrag(smb, kc);
            if (WMODE == 0) {
#pragma unroll
                for (int tm = 0; tm < 2; tm++)
#pragma unroll
                    for (int tn = 0; tn < 8; tn++)
                        mma_f16(c[tm][tn], ah[tm], bh[tn]);
            } else {
#pragma unroll
                for (int tm = 0; tm < 2; tm++)
#pragma unroll
                    for (int tn = 0; tn < 8; tn++)
                        mma_bf16(c[tm][tn], ah[tm], bh[tn]);
#pragma unroll
                for (int tm = 0; tm < 2; tm++)
#pragma unroll
                    for (int tn = 0; tn < 8; tn++)
                        mma_bf16(c[tm][tn], ah[tm], bl[tn]);
#pragma unroll
                for (int tm = 0; tm < 2; tm++)
#pragma unroll
                    for (int tn = 0; tn < 8; tn++)
                        mma_bf16(c[tm][tn], al[tm], bh[tn]);
            }
        }
    }

    const int g = lane >> 2;
    const int t4 = lane & 3;
    const int bm = mb * 128;
    const int bn = nb * 128;
#pragma unroll
    for (int tm = 0; tm < 2; tm++) {
#pragma unroll
        for (int tn = 0; tn < 8; tn++) {
            int row0 = bm + warpM * 32 + tm * 16 + g;
            int col = bn + warpN * 64 + tn * 8 + t4 * 2;
#pragma unroll
            for (int hrow = 0; hrow < 2; hrow++) {
                int m = row0 + hrow * 8;
                float v0 = c[tm][tn][2 * hrow];
                float v1 = c[tm][tn][2 * hrow + 1];
                if (WMODE == 1) {
                    wr_K_img(m, col, v0, v1);
                } else if (WMODE == 2) {
                    wr_V_img(m, col, v0, v1);
                } else {
                    *reinterpret_cast<float2*>(Cout + (size_t)m * 1024 + col) =
                        make_float2(v0, v1);
                }
            }
        }
    }
}

// ---------------------------------------------------------------------------
// Attention item (R15 structure, 64-key tiles): S = K·V^T 3x-bf16; softmax;
// O += P_fp16 · V_fp16hi. SMEM: K 32KB | P 16KB | 2 x (VSB 16KB + VPB 8KB).
// ---------------------------------------------------------------------------
#define ATT_K 0
#define ATT_P 32768
#define ATT_STG 49152
#define ATT_STAGE_SZ 24576

__device__ void attn_item(int mb, int hb) {
    extern __shared__ __align__(1024) char smc[];
    const uint32_t sbase = smem_u32(smc);
    const int tid = threadIdx.x;
    const int lane = tid & 31;
    const int w = tid >> 5;
    const int g = lane >> 2;
    const int t4 = lane & 3;
    const float SC = -32.0f * 1.4426950408889634f;

    const char* KAg = (const char*)g_KA + (size_t)(hb * 16 + mb) * 32768;
    const char* VSBg = (const char*)g_VSB + (size_t)hb * 32 * 16384;
    const char* VPBg = (const char*)g_VPB + (size_t)hb * 64 * 4096;

    auto issue_stage = [&](int i) {
        uint32_t stg = (uint32_t)(ATT_STG + (i & 1) * ATT_STAGE_SZ);
        if (tid < 128) {
            uint32_t d = sbase + stg + (uint32_t)tid * 128;
            const char* s = VSBg + (size_t)i * 16384 + tid * 128;
#pragma unroll
            for (int j = 0; j < 8; j++) CP16(d + j * 16, s + j * 16);
        } else {
            uint32_t d = sbase + stg + 16384 + (uint32_t)(tid - 128) * 64;
            const char* s = VPBg + (size_t)(2 * i) * 4096 + (tid - 128) * 64;
#pragma unroll
            for (int j = 0; j < 4; j++) CP16(d + j * 16, s + j * 16);
        }
        CP_COMMIT();
    };

    {
        uint32_t d = sbase + (uint32_t)tid * 128;
        const char* s = KAg + tid * 128;
#pragma unroll
        for (int j = 0; j < 8; j++) CP16(d + j * 16, s + j * 16);
    }
    issue_stage(0);
    issue_stage(1);

    float o[8][4];
#pragma unroll
    for (int tn = 0; tn < 8; tn++)
#pragma unroll
        for (int q = 0; q < 4; q++) o[tn][q] = 0.0f;
    float m0 = -INFINITY, m1 = -INFINITY, l0 = 0.0f, l1 = 0.0f;

    for (int i = 0; i < 32; i++) {
        if (i < 31) CP_WAIT(1); else CP_WAIT(0);
        __syncthreads();
        const uint32_t stg = (uint32_t)(ATT_STG + (i & 1) * ATT_STAGE_SZ);

        float s[8][4];
#pragma unroll
        for (int tn = 0; tn < 8; tn++)
#pragma unroll
            for (int q = 0; q < 4; q++) s[tn][q] = 0.0f;

        uint32_t ah[4], al[4], bh[8][2], bl[8][2];
#pragma unroll
        for (int kc = 0; kc < 4; kc++) {
            int dc = kc >> 1;
            int kci = kc & 1;
            uint32_t aoff = (uint32_t)(ATT_K + dc * 16384) +
                            SW128((uint32_t)(kci * 8 + w) * 512 + lane * 16);
            uint4 h4 = *reinterpret_cast<const uint4*>(smc + aoff);
            uint4 l4 = *reinterpret_cast<const uint4*>(smc + aoff + 8192);
            ah[0] = h4.x; ah[1] = h4.y; ah[2] = h4.z; ah[3] = h4.w;
            al[0] = l4.x; al[1] = l4.y; al[2] = l4.z; al[3] = l4.w;
#pragma unroll
            for (int tn = 0; tn < 8; tn++) {
                uint32_t boff = stg + (uint32_t)(dc * 8192) +
                                SW128((uint32_t)(kci * 8 + tn) * 256 + lane * 8);
                uint2 bh2 = *reinterpret_cast<const uint2*>(smc + boff);
                uint2 bl2 = *reinterpret_cast<const uint2*>(smc + boff + 4096);
                bh[tn][0] = bh2.x; bh[tn][1] = bh2.y;
                bl[tn][0] = bl2.x; bl[tn][1] = bl2.y;
            }
#pragma unroll
            for (int tn = 0; tn < 8; tn++) mma_bf16(s[tn], ah, bh[tn]);
#pragma unroll
            for (int tn = 0; tn < 8; tn++) mma_bf16(s[tn], ah, bl[tn]);
#pragma unroll
            for (int tn = 0; tn < 8; tn++) mma_bf16(s[tn], al, bh[tn]);
        }

#pragma unroll
        for (int tn = 0; tn < 8; tn++)
#pragma unroll
            for (int q = 0; q < 4; q++) s[tn][q] *= SC;

        float mx0 = s[0][0], mx1 = s[0][2];
#pragma unroll
        for (int tn = 0; tn < 8; tn++) {
            mx0 = fmaxf(mx0, fmaxf(s[tn][0], s[tn][1]));
            mx1 = fmaxf(mx1, fmaxf(s[tn][2], s[tn][3]));
        }
        mx0 = fmaxf(mx0, __shfl_xor_sync(0xffffffffu, mx0, 1));
        mx0 = fmaxf(mx0, __shfl_xor_sync(0xffffffffu, mx0, 2));
        mx1 = fmaxf(mx1, __shfl_xor_sync(0xffffffffu, mx1, 1));
        mx1 = fmaxf(mx1, __shfl_xor_sync(0xffffffffu, mx1, 2));

        float mn0 = fmaxf(m0, mx0), mn1 = fmaxf(m1, mx1);
        float al0 = fast_exp2(m0 - mn0), al1 = fast_exp2(m1 - mn1);
        m0 = mn0; m1 = mn1;

        float rs0 = 0.0f, rs1 = 0.0f;
        const int r0 = w * 16 + g;
#pragma unroll
        for (int tn = 0; tn < 8; tn++) {
            int pairIdx = tn * 4 + t4;
#pragma unroll
            for (int hrow = 0; hrow < 2; hrow++) {
                float mnv = hrow ? mn1 : mn0;
                float p0 = fast_exp2(s[tn][2 * hrow] - mnv);
                float p1 = fast_exp2(s[tn][2 * hrow + 1] - mnv);
                __half2 ph = __floats2half2_rn(p0, p1);
                uint32_t pw = *reinterpret_cast<uint32_t*>(&ph);
                float pq0 = __low2float(ph);
                float pq1 = __high2float(ph);
                if (hrow) rs1 += pq0 + pq1; else rs0 += pq0 + pq1;
                int row = r0 + hrow * 8;
                *reinterpret_cast<uint32_t*>(
                    smc + ATT_P + (pairIdx >> 4) * 8192 +
                    A16_off(row, pairIdx & 15)) = pw;
            }
        }
        rs0 += __shfl_xor_sync(0xffffffffu, rs0, 1);
        rs0 += __shfl_xor_sync(0xffffffffu, rs0, 2);
        rs1 += __shfl_xor_sync(0xffffffffu, rs1, 1);
        rs1 += __shfl_xor_sync(0xffffffffu, rs1, 2);
        l0 = l0 * al0 + rs0;
        l1 = l1 * al1 + rs1;
#pragma unroll
        for (int tn = 0; tn < 8; tn++) {
            o[tn][0] *= al0; o[tn][1] *= al0;
            o[tn][2] *= al1; o[tn][3] *= al1;
        }
        __syncwarp();

#pragma unroll
        for (int kk = 0; kk < 4; kk++) {
            int kc = kk >> 1;
            int kci = kk & 1;
            uint32_t pa[4], vh[8][2];
            uint32_t poff = (uint32_t)(ATT_P + kc * 8192) +
                            SW128((uint32_t)(kci * 8 + w) * 512 + lane * 16);
            uint4 p4 = *reinterpret_cast<const uint4*>(smc + poff);
            pa[0] = p4.x; pa[1] = p4.y; pa[2] = p4.z; pa[3] = p4.w;
#pragma unroll
            for (int tn = 0; tn < 8; tn++) {
                uint32_t voff = stg + (uint32_t)(16384 + kc * 4096) +
                                SW128((uint32_t)(kci * 8 + tn) * 256 + lane * 8);
                uint2 vh2 = *reinterpret_cast<const uint2*>(smc + voff);
                vh[tn][0] = vh2.x; vh[tn][1] = vh2.y;
            }
#pragma unroll
            for (int tn = 0; tn < 8; tn++) mma_f16(o[tn], pa, vh[tn]);
        }
        __syncthreads();
        if (i < 30) issue_stage(i + 2);
    }

    const int b = hb >> 4;
    const int h = hb & 15;
    const float inv0 = 1.0f / l0, inv1 = 1.0f / l1;
    const int rbase = b * 2048 + mb * 128 + w * 16 + g;
#pragma unroll
    for (int tn = 0; tn < 8; tn++) {
        int d0 = h * 64 + tn * 8 + t4 * 2;
#pragma unroll
        for (int hrow = 0; hrow < 2; hrow++) {
            int row = rbase + hrow * 8;
            float inv = hrow ? inv1 : inv0;
            float v0 = o[tn][2 * hrow] * inv;
            float v1 = o[tn][2 * hrow + 1] * inv;
            char* blk = (char*)g_OA + (size_t)((row >> 7) * 32 + (d0 >> 5)) * 16384;
            uint32_t off = A16_off(row & 127, (d0 & 31) >> 1);
            *reinterpret_cast<uint32_t*>(blk + off) = f16x2_pack(v0, v1);
        }
    }
}

// ---------------------------------------------------------------------------
// Persistent megakernel: work queue over 1280 items with dependency counters.
//  id 0..511    : proj   (z = id>>8, mb = (id&255)>>3, nb = id&7)
//  id 512..1023 : attn   (hb = (id-512)>>4, mbq = (id-512)&15)
//  id 1024..1279: oproj  (mb = (id-1024)>>3, nb = (id-1024)&7)
// ---------------------------------------------------------------------------
__device__ __forceinline__ void wait_cnt(int* p, int target) {
    while (atomicAdd(p, 0) < target) __nanosleep(200);
    __threadfence();
}

__global__ __launch_bounds__(256, 2) void mega_kernel(float* __restrict__ out) {
    __shared__ int s_id;
    const int tid = threadIdx.x;
    for (;;) {
        __syncthreads();   // protects s_id and SMEM reuse across items
        if (tid == 0) s_id = atomicAdd(&g_next, 1);
        __syncthreads();
        const int id = s_id;
        if (id >= 1280) return;

        if (id < 512) {
            int z = id >> 8;
            int rem = id & 255;
            int mb = rem >> 3;
            int nb = rem & 7;
            if (z == 0)
                gemm_img_body<1>(g_xA, g_WkB, nullptr, mb, nb);
            else
                gemm_img_body<2>(g_xA, g_WvB, nullptr, mb, nb);
            __syncthreads();
            if (tid == 0) {
                __threadfence();
                atomicAdd(&g_projdone[z * 16 + nb * 2 + (mb >> 4)], 1);
            }
        } else if (id < 1024) {
            int a = id - 512;
            int hb = a >> 4;
            int mbq = a & 15;
            int b = hb >> 4;
            int nbb = (hb & 15) >> 1;
            if (tid == 0) {
                wait_cnt(&g_projdone[nbb * 2 + b], 16);        // K proj done
                wait_cnt(&g_projdone[16 + nbb * 2 + b], 16);   // V proj done
            }
            __syncthreads();
            attn_item(mbq, hb);
            __syncthreads();
            if (tid == 0) {
                __threadfence();
                atomicAdd(&g_attndone[b * 16 + mbq], 1);
            }
        } else {
            int o = id - 1024;
            int mb = o >> 3;
            int nb = o & 7;
            if (tid == 0) wait_cnt(&g_attndone[mb], 16);
            __syncthreads();
            gemm_img_body<0>(g_OA, g_WoB, out, mb, nb);
        }
    }
}

extern "C" void kernel_launch(void* const* d_in, const int* in_sizes, int n_in,
                              void* d_out, int out_size) {
    const float* x = (const float*)d_in[0];
    // d_in[1] = Wq (dead code in the reference dataflow)
    const float* Wk = (const float*)d_in[2];
    const float* Wv = (const float*)d_in[3];
    const float* Wo = (const float*)d_in[4];
    float* out = (float*)d_out;

    cudaFuncSetAttribute(mega_kernel, cudaFuncAttributeMaxDynamicSharedMemorySize,
                         MEGA_SMEM_BYTES);

    // 1) Reset work-queue state
    init_kernel<<<1, 64>>>();

    // 2) Pre-split inputs into fragment images (x/Wk/Wv bf16, Wo fp16 hi-only)
    split_kernel<<<dim3(32, 32, 4), 128>>>(x, Wk, Wv, Wo);

    // 3) Persistent megakernel: proj -> attn -> oproj via work queue
    mega_kernel<<<304, 256, MEGA_SMEM_BYTES>>>(out);
}